// round 16
// baseline (speedup 1.0000x reference)
#include <cuda_runtime.h>
#include <cuda_bf16.h>
#include <math.h>

// ---------------- problem constants ----------------
#define B_      64
#define T_      512
#define WIN_    40
#define KS_     3
#define NPT_    9          // KS*KS
#define CF_     8
#define H_      510        // T - 2
#define WO_     38         // WIN - 2
#define GIN_    304        // WO_*CF_
#define GH_     32
#define G3_     96         // 3*GH
#define NTOK_   (H_ * B_)  // 32640

// producer smem layout (floats)
#define SA_PAD  34                  // 32 batches + 2 pad
#define SA_SZ   (GIN_ * SA_PAD)     // 10336
#define SW_W    196
#define SW_SZ   (16 * SW_W)         // 3136
#define SC_OFF  (SA_SZ + SW_SZ)     // 13472
#define SMEM_FLOATS (SC_OFF + 162 + 18 + 72 + 8 + 96)   // 13828
#define SMEM_BYTES  (SMEM_FLOATS * 4)                    // 55312

typedef unsigned long long ull;

// ---------------- scratch (device globals; no cudaMalloc allowed) -------------
__device__ float g_xp [NTOK_ * G3_ + 2 * G3_]; // (b,t,g), +2 rows pad
__device__ float g_enc[B_ * H_ * GH_];         // (b,t,g)
__device__ float g_att[B_ * H_ * GH_];         // (b,t,g)
__device__ float g_wt [GIN_ * 2 * G3_];        // [k][2g|2g+1] duplicated

// ---------------- f32x2 packed math helpers ----------------
__device__ __forceinline__ ull ffma2(ull a, ull b, ull c) {
    ull d;
    asm("fma.rn.f32x2 %0, %1, %2, %3;" : "=l"(d) : "l"(a), "l"(b), "l"(c));
    return d;
}
__device__ __forceinline__ ull fadd2(ull a, ull b) {
    ull d;
    asm("add.rn.f32x2 %0, %1, %2;" : "=l"(d) : "l"(a), "l"(b));
    return d;
}
__device__ __forceinline__ ull pack2(float x, float y) {
    ull v;
    asm("mov.b64 %0, {%1, %2};" : "=l"(v) : "f"(x), "f"(y));
    return v;
}
__device__ __forceinline__ float2 unpack2(ull v) {
    float2 r;
    asm("mov.b64 {%0, %1}, %2;" : "=f"(r.x), "=f"(r.y) : "l"(v));
    return r;
}
__device__ __forceinline__ float tanha(float x) {
    float r; asm("tanh.approx.f32 %0, %1;" : "=f"(r) : "f"(x)); return r;
}
__device__ __forceinline__ float fsig(float x) {
    return fmaf(0.5f, tanha(0.5f * x), 0.5f);
}
__device__ __forceinline__ float4 max4(float4 a, float4 b) {
    return make_float4(fmaxf(a.x, b.x), fmaxf(a.y, b.y), fmaxf(a.z, b.z), fmaxf(a.w, b.w));
}

// =====================================================================
// Kernel 0: W transpose + duplicate
// =====================================================================
__global__ void k_wprep(const float* __restrict__ w_ih)
{
    int idx = blockIdx.x * blockDim.x + threadIdx.x;
    if (idx >= G3_ * GIN_) return;
    int g = idx / GIN_;
    int k = idx - g * GIN_;
    float v = w_ih[idx];
    *reinterpret_cast<float2*>(&g_wt[k * (2 * G3_) + 2 * g]) = make_float2(v, v);
}

// =====================================================================
// Kernel 1: FUSED deform + x-projection GEMM. One block per time-step.
// FIX vs round-15: constant staging now uses strided loops (162 > 128
// threads — the single-shot `if (tid < 162)` left s_pw[128..161] garbage).
// =====================================================================
__global__ void __launch_bounds__(128) k_prod(
    const float* __restrict__ x,
    const float* __restrict__ p_w,  const float* __restrict__ p_b,
    const float* __restrict__ dcn_w, const float* __restrict__ dcn_b,
    const float* __restrict__ b_ih)
{
    extern __shared__ __align__(16) float smem[];
    int t   = blockIdx.x;
    int tid = threadIdx.x;

    float* s_a = smem;                 // [k][32+pad]
    float* s_w = smem + SA_SZ;         // [16][196]
    float* s_pw  = smem + SC_OFF;      // 162
    float* s_pb  = s_pw + 162;         // 18
    float* s_dw  = s_pb + 18;          // 72
    float* s_db  = s_dw + 72;          // 8
    float* s_bih = s_db + 8;           // 96

    for (int i = tid; i < 2 * NPT_ * NPT_; i += 128) s_pw[i] = p_w[i];
    for (int i = tid; i < 2 * NPT_;       i += 128) s_pb[i] = p_b[i];
    for (int i = tid; i < CF_ * NPT_;     i += 128) s_dw[i] = dcn_w[i];
    for (int i = tid; i < CF_;            i += 128) s_db[i] = dcn_b[i];
    for (int i = tid; i < G3_;            i += 128) s_bih[i] = b_ih[i];
    __syncthreads();

    int tg = tid >> 4;          // 0..7
    int gg = tid & 15;          // 0..15
    int tb = tg * 4;            // 4 local batches
    int gbase = gg * 6;

    for (int P = 0; P < 2; P++) {
        // ---- deform 32 batches for time t into s_a (transposed) ----
        for (int p = tid; p < 32 * WO_; p += 128) {
            int bl = p / WO_;
            int w  = p - bl * WO_;
            int b  = P * 32 + bl;
            const float* xb = x + b * (T_ * WIN_);

            float patch[NPT_];
#pragma unroll
            for (int ky = 0; ky < KS_; ky++)
#pragma unroll
                for (int kx = 0; kx < KS_; kx++)
                    patch[ky * KS_ + kx] = xb[(t + ky) * WIN_ + (w + kx)];

            float off[2 * NPT_];
#pragma unroll
            for (int o = 0; o < 2 * NPT_; o++) off[o] = s_pb[o];
#pragma unroll
            for (int k = 0; k < NPT_; k++) {
                float pv = patch[k];
#pragma unroll
                for (int o = 0; o < 2 * NPT_; o++)
                    off[o] = fmaf(pv, s_pw[o * NPT_ + k], off[o]);
            }

            float acc[CF_];
#pragma unroll
            for (int c = 0; c < CF_; c++) acc[c] = s_db[c];
#pragma unroll
            for (int n = 0; n < NPT_; n++) {
                float py = off[n]        + (float)(n / 3 - 1) + (float)(t + 1);
                float px = off[NPT_ + n] + (float)(n % 3 - 1) + (float)(w + 1);
                py = fminf(fmaxf(py, 0.0f), (float)(T_ - 1));
                px = fminf(fmaxf(px, 0.0f), (float)(WIN_ - 1));
                int y0 = (int)floorf(py);
                int x0 = (int)floorf(px);
                int y1 = min(y0 + 1, T_ - 1);
                int x1 = min(x0 + 1, WIN_ - 1);
                float wy = py - (float)y0;
                float wx = px - (float)x0;
                float g00 = __ldg(&xb[y0 * WIN_ + x0]);
                float g01 = __ldg(&xb[y0 * WIN_ + x1]);
                float g10 = __ldg(&xb[y1 * WIN_ + x0]);
                float g11 = __ldg(&xb[y1 * WIN_ + x1]);
                float top = g00 + wx * (g01 - g00);
                float bot = g10 + wx * (g11 - g10);
                float s   = top + wy * (bot - top);
#pragma unroll
                for (int c = 0; c < CF_; c++)
                    acc[c] = fmaf(s, s_dw[c * NPT_ + n], acc[c]);
            }
#pragma unroll
            for (int c = 0; c < CF_; c++)
                s_a[(w * CF_ + c) * SA_PAD + bl] = acc[c];
        }
        __syncthreads();

        // ---- gemm: 32 batches x 96 g, f32x2 ----
        ull acc2[2][6];
#pragma unroll
        for (int p = 0; p < 2; p++)
#pragma unroll
            for (int j = 0; j < 6; j++) acc2[p][j] = 0ull;

        for (int kt = 0; kt < GIN_ / 16; kt++) {
            const float4* wsrc = reinterpret_cast<const float4*>(g_wt + kt * 16 * (2 * G3_));
            float4 pwv[6];
#pragma unroll
            for (int q = 0; q < 6; q++)
                pwv[q] = wsrc[q * 128 + tid];
            __syncthreads();
#pragma unroll
            for (int q = 0; q < 6; q++) {
                int i = q * 128 + tid;
                int k = i / 48;
                int c4 = i - k * 48;
                *reinterpret_cast<float4*>(&s_w[k * SW_W + c4 * 4]) = pwv[q];
            }
            __syncthreads();

#pragma unroll
            for (int k = 0; k < 16; k++) {
                const ull* ap = reinterpret_cast<const ull*>(&s_a[(kt * 16 + k) * SA_PAD + tb]);
                ull a0 = ap[0], a1 = ap[1];
                const ull* wp = reinterpret_cast<const ull*>(&s_w[k * SW_W + 2 * gbase]);
                ull w0 = wp[0], w1 = wp[1], w2v = wp[2], w3v = wp[3], w4 = wp[4], w5 = wp[5];
                acc2[0][0] = ffma2(a0, w0, acc2[0][0]);
                acc2[1][0] = ffma2(a1, w0, acc2[1][0]);
                acc2[0][1] = ffma2(a0, w1, acc2[0][1]);
                acc2[1][1] = ffma2(a1, w1, acc2[1][1]);
                acc2[0][2] = ffma2(a0, w2v, acc2[0][2]);
                acc2[1][2] = ffma2(a1, w2v, acc2[1][2]);
                acc2[0][3] = ffma2(a0, w3v, acc2[0][3]);
                acc2[1][3] = ffma2(a1, w3v, acc2[1][3]);
                acc2[0][4] = ffma2(a0, w4, acc2[0][4]);
                acc2[1][4] = ffma2(a1, w4, acc2[1][4]);
                acc2[0][5] = ffma2(a0, w5, acc2[0][5]);
                acc2[1][5] = ffma2(a1, w5, acc2[1][5]);
            }
        }

        // ---- epilogue: 4 batches x 6 g -> g_xp (b,t,g) ----
#pragma unroll
        for (int p = 0; p < 2; p++) {
            int b0 = P * 32 + tb + 2 * p;
            float lo[6], hi[6];
#pragma unroll
            for (int j = 0; j < 6; j++) {
                float2 v = unpack2(acc2[p][j]);
                lo[j] = v.x + s_bih[gbase + j];
                hi[j] = v.y + s_bih[gbase + j];
            }
            float2* o0 = reinterpret_cast<float2*>(g_xp + ((size_t)b0 * H_ + t) * G3_ + gbase);
            float2* o1 = reinterpret_cast<float2*>(g_xp + ((size_t)(b0 + 1) * H_ + t) * G3_ + gbase);
            o0[0] = make_float2(lo[0], lo[1]);
            o0[1] = make_float2(lo[2], lo[3]);
            o0[2] = make_float2(lo[4], lo[5]);
            o1[0] = make_float2(hi[0], hi[1]);
            o1[1] = make_float2(hi[2], hi[3]);
            o1[2] = make_float2(hi[4], hi[5]);
        }
        __syncthreads();   // s_a reuse in next pass
    }
}

// =====================================================================
// Kernel 2: GRU scan — round-13 proven: smem h-exchange,
// branchless prefetch, depth-4 chains.
// =====================================================================
__global__ void __launch_bounds__(32) k_gru(const float* __restrict__ w_hh,
                                            const float* __restrict__ b_hh)
{
    __shared__ __align__(16) float hb[2][GH_];
    int b = blockIdx.x;
    int l = threadIdx.x;

    ull wr2[16], wz2[16], wn2[16];
    const float2* wr = reinterpret_cast<const float2*>(w_hh + (0 * GH_ + l) * GH_);
    const float2* wz = reinterpret_cast<const float2*>(w_hh + (1 * GH_ + l) * GH_);
    const float2* wn = reinterpret_cast<const float2*>(w_hh + (2 * GH_ + l) * GH_);
#pragma unroll
    for (int k = 0; k < 16; k++) {
        float2 a = wr[k]; wr2[k] = pack2(a.x, a.y);
        float2 c = wz[k]; wz2[k] = pack2(c.x, c.y);
        float2 d = wn[k]; wn2[k] = pack2(d.x, d.y);
    }
    float br = b_hh[l], bz = b_hh[GH_ + l], bn = b_hh[2 * GH_ + l];

    float h = 0.0f;
    const float* xpb = g_xp + (size_t)b * H_ * G3_;
    float* encb = g_enc + (size_t)b * H_ * GH_;

    float xr0 = xpb[l],        xz0 = xpb[GH_ + l],        xn0 = xpb[2 * GH_ + l];
    float xr1 = xpb[G3_ + l],  xz1 = xpb[G3_ + GH_ + l],  xn1 = xpb[G3_ + 2 * GH_ + l];

    for (int t = 0; t < H_; t++) {
        const float* row = xpb + (size_t)(t + 2) * G3_;
        float xr2 = row[l], xz2 = row[GH_ + l], xn2 = row[2 * GH_ + l];

        hb[t & 1][l] = h;
        __syncwarp();
        const ulonglong2* hp8 = reinterpret_cast<const ulonglong2*>(&hb[t & 1][0]);
        ulonglong2 hq[8];
#pragma unroll
        for (int i = 0; i < 8; i++) hq[i] = hp8[i];
        ull hp[16];
#pragma unroll
        for (int i = 0; i < 8; i++) { hp[2 * i] = hq[i].x; hp[2 * i + 1] = hq[i].y; }

        ull arA = 0ull, arB = 0ull, arC = 0ull, arD = 0ull;
        ull anA = 0ull, anB = 0ull, anC = 0ull, anD = 0ull;
#pragma unroll
        for (int kk = 0; kk < 4; kk++) {
            arA = ffma2(hp[4 * kk + 0], wr2[4 * kk + 0], arA);
            anA = ffma2(hp[4 * kk + 0], wn2[4 * kk + 0], anA);
            arB = ffma2(hp[4 * kk + 1], wr2[4 * kk + 1], arB);
            anB = ffma2(hp[4 * kk + 1], wn2[4 * kk + 1], anB);
            arC = ffma2(hp[4 * kk + 2], wr2[4 * kk + 2], arC);
            anC = ffma2(hp[4 * kk + 2], wn2[4 * kk + 2], anC);
            arD = ffma2(hp[4 * kk + 3], wr2[4 * kk + 3], arD);
            anD = ffma2(hp[4 * kk + 3], wn2[4 * kk + 3], anD);
        }
        float2 rr = unpack2(fadd2(fadd2(arA, arB), fadd2(arC, arD)));
        float rg = fsig(xr0 + rr.x + rr.y + br);

        ull azA = 0ull, azB = 0ull, azC = 0ull, azD = 0ull;
#pragma unroll
        for (int kk = 0; kk < 4; kk++) {
            azA = ffma2(hp[4 * kk + 0], wz2[4 * kk + 0], azA);
            azB = ffma2(hp[4 * kk + 1], wz2[4 * kk + 1], azB);
            azC = ffma2(hp[4 * kk + 2], wz2[4 * kk + 2], azC);
            azD = ffma2(hp[4 * kk + 3], wz2[4 * kk + 3], azD);
        }
        float2 nn = unpack2(fadd2(fadd2(anA, anB), fadd2(anC, anD)));
        float an = nn.x + nn.y + bn;
        float ng = tanha(fmaf(rg, an, xn0));

        float2 zz = unpack2(fadd2(fadd2(azA, azB), fadd2(azC, azD)));
        float zg = fsig(xz0 + zz.x + zz.y + bz);

        h = fmaf(zg, h - ng, ng);

        encb[t * GH_ + l] = h;
        xr0 = xr1; xz0 = xz1; xn0 = xn1;
        xr1 = xr2; xz1 = xz2; xn1 = xn2;
    }
}

// =====================================================================
// Kernel 3: attention scores (round-4 proven): 255 blocks,
// one thread per token, smem weights, f32x2, tanh.approx -> g_att
// =====================================================================
__global__ void __launch_bounds__(128) k_scores(
    const float* __restrict__ w1, const float* __restrict__ b1,
    const float* __restrict__ w2, const float* __restrict__ b2)
{
    __shared__ __align__(16) float sw1[GH_ * GH_];
    __shared__ __align__(16) float sw2[GH_ * GH_];
    __shared__ float sb1[GH_], sb2[GH_];

    int tid = threadIdx.x;
#pragma unroll
    for (int q = 0; q < 8; q++) {
        sw1[q * 128 + tid] = w1[q * 128 + tid];
        sw2[q * 128 + tid] = w2[q * 128 + tid];
    }
    if (tid < GH_) { sb1[tid] = b1[tid]; sb2[tid] = b2[tid]; }
    __syncthreads();

    int tok = blockIdx.x * 128 + tid;
    const float* erow = g_enc + (size_t)tok * GH_;

    ull e2[16];
#pragma unroll
    for (int i = 0; i < 8; i++) {
        ulonglong2 v = reinterpret_cast<const ulonglong2*>(erow)[i];
        e2[2 * i] = v.x; e2[2 * i + 1] = v.y;
    }

    ull h2[16];
#pragma unroll 4
    for (int j = 0; j < GH_; j += 2) {
        const ulonglong2* wA = reinterpret_cast<const ulonglong2*>(sw1 + j * GH_);
        const ulonglong2* wB = reinterpret_cast<const ulonglong2*>(sw1 + (j + 1) * GH_);
        ull a0 = 0ull, a1 = 0ull, c0 = 0ull, c1 = 0ull;
#pragma unroll
        for (int k = 0; k < 8; k++) {
            ulonglong2 wa = wA[k], wb = wB[k];
            a0 = ffma2(e2[2 * k],     wa.x, a0);
            a1 = ffma2(e2[2 * k + 1], wa.y, a1);
            c0 = ffma2(e2[2 * k],     wb.x, c0);
            c1 = ffma2(e2[2 * k + 1], wb.y, c1);
        }
        float2 fa = unpack2(fadd2(a0, a1));
        float2 fc = unpack2(fadd2(c0, c1));
        h2[j >> 1] = pack2(tanha(fa.x + fa.y + sb1[j]),
                           tanha(fc.x + fc.y + sb1[j + 1]));
    }

    float outv[GH_];
#pragma unroll 4
    for (int g = 0; g < GH_; g += 2) {
        const ulonglong2* wA = reinterpret_cast<const ulonglong2*>(sw2 + g * GH_);
        const ulonglong2* wB = reinterpret_cast<const ulonglong2*>(sw2 + (g + 1) * GH_);
        ull a0 = 0ull, a1 = 0ull, c0 = 0ull, c1 = 0ull;
#pragma unroll
        for (int k = 0; k < 8; k++) {
            ulonglong2 wa = wA[k], wb = wB[k];
            a0 = ffma2(h2[2 * k],     wa.x, a0);
            a1 = ffma2(h2[2 * k + 1], wa.y, a1);
            c0 = ffma2(h2[2 * k],     wb.x, c0);
            c1 = ffma2(h2[2 * k + 1], wb.y, c1);
        }
        float2 fa = unpack2(fadd2(a0, a1));
        float2 fc = unpack2(fadd2(c0, c1));
        outv[g]     = fa.x + fa.y + sb2[g];
        outv[g + 1] = fc.x + fc.y + sb2[g + 1];
    }

    float* arow = g_att + (size_t)tok * GH_;
#pragma unroll
    for (int i = 0; i < 8; i++)
        reinterpret_cast<float4*>(arow)[i] =
            make_float4(outv[4 * i], outv[4 * i + 1], outv[4 * i + 2], outv[4 * i + 3]);
}

// =====================================================================
// Kernel 4: softmax over t + pool + head. (proven)
// =====================================================================
__global__ void __launch_bounds__(512) k_pool(
    const float* __restrict__ w3, const float* __restrict__ b3,
    float* __restrict__ out)
{
    int b    = blockIdx.x;
    int tid  = threadIdx.x;
    int part = tid >> 3;
    int gq   = tid & 7;
    int wid  = tid >> 5;

    const float4* encb = reinterpret_cast<const float4*>(g_enc + (size_t)b * H_ * GH_);
    const float4* attb = reinterpret_cast<const float4*>(g_att + (size_t)b * H_ * GH_);

    __shared__ float4 red[16][8];
    __shared__ float4 redp[16][8];
    __shared__ float4 mg4s[8];
    __shared__ float pooled[GH_];

    float4 m = make_float4(-1e30f, -1e30f, -1e30f, -1e30f);
    for (int t = part; t < H_; t += 64)
        m = max4(m, attb[t * 8 + gq]);
#pragma unroll
    for (int s = 8; s <= 16; s <<= 1) {
        m.x = fmaxf(m.x, __shfl_xor_sync(0xffffffffu, m.x, s));
        m.y = fmaxf(m.y, __shfl_xor_sync(0xffffffffu, m.y, s));
        m.z = fmaxf(m.z, __shfl_xor_sync(0xffffffffu, m.z, s));
        m.w = fmaxf(m.w, __shfl_xor_sync(0xffffffffu, m.w, s));
    }
    if ((tid & 31) < 8) red[wid][gq] = m;
    __syncthreads();
    if (tid < 8) {
        float4 mm = red[0][tid];
#pragma unroll
        for (int p = 1; p < 16; p++) mm = max4(mm, red[p][tid]);
        mg4s[tid] = mm;
    }
    __syncthreads();
    float4 mg = mg4s[gq];

    float4 se = make_float4(0.f, 0.f, 0.f, 0.f);
    float4 pw = make_float4(0.f, 0.f, 0.f, 0.f);
    for (int t = part; t < H_; t += 64) {
        float4 a = attb[t * 8 + gq];
        float4 e = encb[t * 8 + gq];
        float ex0 = __expf(a.x - mg.x);
        float ex1 = __expf(a.y - mg.y);
        float ex2v = __expf(a.z - mg.z);
        float ex3 = __expf(a.w - mg.w);
        se.x += ex0; se.y += ex1; se.z += ex2v; se.w += ex3;
        pw.x = fmaf(ex0, e.x, pw.x);
        pw.y = fmaf(ex1, e.y, pw.y);
        pw.z = fmaf(ex2v, e.z, pw.z);
        pw.w = fmaf(ex3, e.w, pw.w);
    }
#pragma unroll
    for (int s = 8; s <= 16; s <<= 1) {
        se.x += __shfl_xor_sync(0xffffffffu, se.x, s);
        se.y += __shfl_xor_sync(0xffffffffu, se.y, s);
        se.z += __shfl_xor_sync(0xffffffffu, se.z, s);
        se.w += __shfl_xor_sync(0xffffffffu, se.w, s);
        pw.x += __shfl_xor_sync(0xffffffffu, pw.x, s);
        pw.y += __shfl_xor_sync(0xffffffffu, pw.y, s);
        pw.z += __shfl_xor_sync(0xffffffffu, pw.z, s);
        pw.w += __shfl_xor_sync(0xffffffffu, pw.w, s);
    }
    if ((tid & 31) < 8) { red[wid][gq] = se; redp[wid][gq] = pw; }
    __syncthreads();
    if (tid < 8) {
        float4 ts = red[0][tid];
        float4 tp = redp[0][tid];
#pragma unroll
        for (int p = 1; p < 16; p++) {
            float4 s1 = red[p][tid];
            float4 p1 = redp[p][tid];
            ts.x += s1.x; ts.y += s1.y; ts.z += s1.z; ts.w += s1.w;
            tp.x += p1.x; tp.y += p1.y; tp.z += p1.z; tp.w += p1.w;
        }
        pooled[tid * 4 + 0] = tp.x / ts.x;
        pooled[tid * 4 + 1] = tp.y / ts.y;
        pooled[tid * 4 + 2] = tp.z / ts.z;
        pooled[tid * 4 + 3] = tp.w / ts.w;
    }
    __syncthreads();

    if (tid < 64) {
        int o  = tid >> 5;
        int gg = tid & 31;
        float v = pooled[gg] * __ldg(&w3[o * GH_ + gg]);
#pragma unroll
        for (int s = 16; s > 0; s >>= 1)
            v += __shfl_xor_sync(0xffffffffu, v, s);
        if (gg == 0)
            out[b * 2 + o] = v + __ldg(&b3[o]);
    }
}

// =====================================================================
extern "C" void kernel_launch(void* const* d_in, const int* in_sizes, int n_in,
                              void* d_out, int out_size)
{
    const float* x     = (const float*)d_in[0];
    const float* p_w   = (const float*)d_in[1];
    const float* p_b   = (const float*)d_in[2];
    const float* dcn_w = (const float*)d_in[3];
    const float* dcn_b = (const float*)d_in[4];
    const float* w_ih  = (const float*)d_in[5];
    const float* w_hh  = (const float*)d_in[6];
    const float* b_ih  = (const float*)d_in[7];
    const float* b_hh  = (const float*)d_in[8];
    const float* w1    = (const float*)d_in[9];
    const float* b1    = (const float*)d_in[10];
    const float* w2    = (const float*)d_in[11];
    const float* b2    = (const float*)d_in[12];
    const float* w3    = (const float*)d_in[13];
    const float* b3    = (const float*)d_in[14];
    float* out = (float*)d_out;

    cudaFuncSetAttribute(k_prod, cudaFuncAttributeMaxDynamicSharedMemorySize, SMEM_BYTES);

    {
        int n = G3_ * GIN_;
        k_wprep<<<(n + 255) / 256, 256>>>(w_ih);
    }
    {
        k_prod<<<H_, 128, SMEM_BYTES>>>(x, p_w, p_b, dcn_w, dcn_b, b_ih);  // 510 blocks
    }
    {
        k_gru<<<B_, GH_>>>(w_hh, b_hh);             // 64 blocks, 1 warp/batch
    }
    {
        k_scores<<<NTOK_ / 128, 128>>>(w1, b1, w2, b2);  // 255 blocks
    }
    {
        k_pool<<<B_, 512>>>(w3, b3, out);
    }
}

// round 17
// speedup vs baseline: 1.3034x; 1.3034x over previous
#include <cuda_runtime.h>
#include <cuda_bf16.h>
#include <math.h>

// ---------------- problem constants ----------------
#define B_      64
#define T_      512
#define WIN_    40
#define KS_     3
#define NPT_    9          // KS*KS
#define CF_     8
#define H_      510        // T - 2
#define WO_     38         // WIN - 2
#define GIN_    304        // WO_*CF_
#define GH_     32
#define G3_     96         // 3*GH
#define NTOK_   (H_ * B_)  // 32640

#define CH_     102        // GRU chunk (5 * 102 = 510)
#define NCH_    5
#define NGRUB_  16         // 16 gru blocks x 4 warps = 64 batches
#define NGEMB_  255        // gemm blocks, 2 timesteps each
#define NBLK_   (NGRUB_ + NGEMB_)  // 271

typedef unsigned long long ull;

// ---------------- scratch (device globals; no cudaMalloc allowed) -------------
__device__ float g_seq[NTOK_ * GIN_];          // (t,b,f)
__device__ float g_xp [NTOK_ * G3_ + 2 * G3_]; // (b,t,g), +2 rows pad
__device__ float g_enc[B_ * H_ * GH_];         // (b,t,g)
__device__ float g_att[B_ * H_ * GH_];         // (b,t,g)
__device__ float g_wt [GIN_ * 2 * G3_];        // [k][2g|2g+1] duplicated
__device__ int   g_cnt[NCH_];                  // gemm completion per chunk

// ---------------- f32x2 packed math helpers ----------------
__device__ __forceinline__ ull ffma2(ull a, ull b, ull c) {
    ull d;
    asm("fma.rn.f32x2 %0, %1, %2, %3;" : "=l"(d) : "l"(a), "l"(b), "l"(c));
    return d;
}
__device__ __forceinline__ ull fadd2(ull a, ull b) {
    ull d;
    asm("add.rn.f32x2 %0, %1, %2;" : "=l"(d) : "l"(a), "l"(b));
    return d;
}
__device__ __forceinline__ ull pack2(float x, float y) {
    ull v;
    asm("mov.b64 %0, {%1, %2};" : "=l"(v) : "f"(x), "f"(y));
    return v;
}
__device__ __forceinline__ float2 unpack2(ull v) {
    float2 r;
    asm("mov.b64 {%0, %1}, %2;" : "=f"(r.x), "=f"(r.y) : "l"(v));
    return r;
}
__device__ __forceinline__ float tanha(float x) {
    float r; asm("tanh.approx.f32 %0, %1;" : "=f"(r) : "f"(x)); return r;
}
__device__ __forceinline__ float fsig(float x) {
    return fmaf(0.5f, tanha(0.5f * x), 0.5f);
}
__device__ __forceinline__ float4 max4(float4 a, float4 b) {
    return make_float4(fmaxf(a.x, b.x), fmaxf(a.y, b.y), fmaxf(a.z, b.z), fmaxf(a.w, b.w));
}
__device__ __forceinline__ float ldcg_f(const float* p) {
    float v;
    asm volatile("ld.global.cg.f32 %0, [%1];" : "=f"(v) : "l"(p));
    return v;
}

// =====================================================================
// Kernel 1: deformable conv -> g_seq  (+ merged w_ih transpose/dup
// + flag reset for replay safety)
// =====================================================================
__global__ void k_deform(const float* __restrict__ x,
                         const float* __restrict__ p_w,
                         const float* __restrict__ p_b,
                         const float* __restrict__ dcn_w,
                         const float* __restrict__ dcn_b,
                         const float* __restrict__ w_ih)
{
    __shared__ float s_pw[2 * NPT_ * NPT_];
    __shared__ float s_pb[2 * NPT_];
    __shared__ float s_dw[CF_ * NPT_];
    __shared__ float s_db[CF_];

    int tid = threadIdx.x;
    int gid = blockIdx.x * blockDim.x + tid;

    if (gid < NCH_) g_cnt[gid] = 0;   // reset pipeline flags each replay

    // merged wprep
    if (gid < G3_ * GIN_) {
        int g = gid / GIN_;
        int k = gid - g * GIN_;
        float v = w_ih[gid];
        *reinterpret_cast<float2*>(&g_wt[k * (2 * G3_) + 2 * g]) = make_float2(v, v);
    }

    for (int i = tid; i < 2 * NPT_ * NPT_; i += blockDim.x) s_pw[i] = p_w[i];
    for (int i = tid; i < 2 * NPT_;       i += blockDim.x) s_pb[i] = p_b[i];
    for (int i = tid; i < CF_ * NPT_;     i += blockDim.x) s_dw[i] = dcn_w[i];
    for (int i = tid; i < CF_;            i += blockDim.x) s_db[i] = dcn_b[i];
    __syncthreads();

    int idx = gid;
    const int total = B_ * H_ * WO_;
    if (idx >= total) return;

    int w  = idx % WO_;
    int b  = (idx / WO_) % B_;
    int t  = idx / (WO_ * B_);

    const float* xb = x + b * (T_ * WIN_);

    float patch[NPT_];
#pragma unroll
    for (int ky = 0; ky < KS_; ky++)
#pragma unroll
        for (int kx = 0; kx < KS_; kx++)
            patch[ky * KS_ + kx] = xb[(t + ky) * WIN_ + (w + kx)];

    float off[2 * NPT_];
#pragma unroll
    for (int o = 0; o < 2 * NPT_; o++) off[o] = s_pb[o];
#pragma unroll
    for (int k = 0; k < NPT_; k++) {
        float pv = patch[k];
#pragma unroll
        for (int o = 0; o < 2 * NPT_; o++)
            off[o] = fmaf(pv, s_pw[o * NPT_ + k], off[o]);
    }

    float acc[CF_];
#pragma unroll
    for (int c = 0; c < CF_; c++) acc[c] = s_db[c];

#pragma unroll
    for (int n = 0; n < NPT_; n++) {
        float py = off[n]        + (float)(n / 3 - 1) + (float)(t + 1);
        float px = off[NPT_ + n] + (float)(n % 3 - 1) + (float)(w + 1);
        py = fminf(fmaxf(py, 0.0f), (float)(T_ - 1));
        px = fminf(fmaxf(px, 0.0f), (float)(WIN_ - 1));
        int y0 = (int)floorf(py);
        int x0 = (int)floorf(px);
        int y1 = min(y0 + 1, T_ - 1);
        int x1 = min(x0 + 1, WIN_ - 1);
        float wy = py - (float)y0;
        float wx = px - (float)x0;
        float g00 = __ldg(&xb[y0 * WIN_ + x0]);
        float g01 = __ldg(&xb[y0 * WIN_ + x1]);
        float g10 = __ldg(&xb[y1 * WIN_ + x0]);
        float g11 = __ldg(&xb[y1 * WIN_ + x1]);
        float top = g00 + wx * (g01 - g00);
        float bot = g10 + wx * (g11 - g10);
        float s   = top + wy * (bot - top);
#pragma unroll
        for (int c = 0; c < CF_; c++)
            acc[c] = fmaf(s, s_dw[c * NPT_ + n], acc[c]);
    }

    float* dst = g_seq + (size_t)(t * B_ + b) * GIN_ + w * CF_;
    *reinterpret_cast<float4*>(dst)     = make_float4(acc[0], acc[1], acc[2], acc[3]);
    *reinterpret_cast<float4*>(dst + 4) = make_float4(acc[4], acc[5], acc[6], acc[7]);
}

// =====================================================================
// Kernel 2: k_mid — GEMM + GRU pipelined via per-chunk flags.
//   bid 0..15  : GRU, warp w -> batch bid*4+w (round-8 proven body, shfl)
//   bid 16..270: gemm block j = bid-16, timesteps t=j and t=j+255
//                (round-14 proven body with base = t*64)
// =====================================================================
#define TM_ 64
#define KT_ 16
#define NKT_ (GIN_ / KT_)     // 19
#define SA_W (TM_ + 2)        // 66
#define SW_W (2 * G3_ + 4)    // 196

__global__ void __launch_bounds__(128) k_mid(
    const float* __restrict__ b_ih,
    const float* __restrict__ w_hh, const float* __restrict__ b_hh)
{
    __shared__ __align__(16) float sa[2][KT_][SA_W];
    __shared__ __align__(16) float sw[2][KT_][SW_W];

    int bid = blockIdx.x;
    int tid = threadIdx.x;

    // =========================== GRU ===========================
    if (bid < NGRUB_) {
        int wid  = tid >> 5;
        int lane = tid & 31;
        int b    = bid * 4 + wid;

        ull wr2[16], wz2[16], wn2[16];
        const float2* wr = reinterpret_cast<const float2*>(w_hh + (0 * GH_ + lane) * GH_);
        const float2* wz = reinterpret_cast<const float2*>(w_hh + (1 * GH_ + lane) * GH_);
        const float2* wn = reinterpret_cast<const float2*>(w_hh + (2 * GH_ + lane) * GH_);
#pragma unroll
        for (int k = 0; k < 16; k++) {
            float2 a = wr[k]; wr2[k] = pack2(a.x, a.y);
            float2 c = wz[k]; wz2[k] = pack2(c.x, c.y);
            float2 d = wn[k]; wn2[k] = pack2(d.x, d.y);
        }
        float br = b_hh[lane], bz = b_hh[GH_ + lane], bn = b_hh[2 * GH_ + lane];

        float h = 0.0f;
        const float* xpb = g_xp + (size_t)b * H_ * G3_;
        float* encb = g_enc + (size_t)b * H_ * GH_;

        for (int c = 0; c < NCH_; c++) {
            if (lane == 0) {
                while (atomicAdd(&g_cnt[c], 0) < CH_) __nanosleep(128);
            }
            __syncwarp();
            __threadfence();   // acquire

            int cs = c * CH_, ce = cs + CH_;
            const float* r0 = xpb + (size_t)cs * G3_;
            float xr0 = ldcg_f(&r0[lane]), xz0 = ldcg_f(&r0[GH_ + lane]), xn0 = ldcg_f(&r0[2 * GH_ + lane]);
            const float* r1 = r0 + G3_;
            float xr1 = ldcg_f(&r1[lane]), xz1 = ldcg_f(&r1[GH_ + lane]), xn1 = ldcg_f(&r1[2 * GH_ + lane]);

            for (int t = cs; t < ce; t++) {
                int pf = min(t + 2, ce - 1);
                const float* row = xpb + (size_t)pf * G3_;
                float xr2 = ldcg_f(&row[lane]);
                float xz2 = ldcg_f(&row[GH_ + lane]);
                float xn2 = ldcg_f(&row[2 * GH_ + lane]);

                ull hp[16];
#pragma unroll
                for (int kk = 0; kk < 16; kk++) {
                    float e = __shfl_sync(0xffffffffu, h, 2 * kk);
                    float o = __shfl_sync(0xffffffffu, h, 2 * kk + 1);
                    hp[kk] = pack2(e, o);
                }

                ull arA = 0ull, arB = 0ull, arC = 0ull, arD = 0ull;
                ull anA = 0ull, anB = 0ull, anC = 0ull, anD = 0ull;
#pragma unroll
                for (int kk = 0; kk < 4; kk++) {
                    arA = ffma2(hp[4 * kk + 0], wr2[4 * kk + 0], arA);
                    anA = ffma2(hp[4 * kk + 0], wn2[4 * kk + 0], anA);
                    arB = ffma2(hp[4 * kk + 1], wr2[4 * kk + 1], arB);
                    anB = ffma2(hp[4 * kk + 1], wn2[4 * kk + 1], anB);
                    arC = ffma2(hp[4 * kk + 2], wr2[4 * kk + 2], arC);
                    anC = ffma2(hp[4 * kk + 2], wn2[4 * kk + 2], anC);
                    arD = ffma2(hp[4 * kk + 3], wr2[4 * kk + 3], arD);
                    anD = ffma2(hp[4 * kk + 3], wn2[4 * kk + 3], anD);
                }
                float2 rr = unpack2(fadd2(fadd2(arA, arB), fadd2(arC, arD)));
                float rg = fsig(xr0 + rr.x + rr.y + br);

                ull azA = 0ull, azB = 0ull, azC = 0ull, azD = 0ull;
#pragma unroll
                for (int kk = 0; kk < 4; kk++) {
                    azA = ffma2(hp[4 * kk + 0], wz2[4 * kk + 0], azA);
                    azB = ffma2(hp[4 * kk + 1], wz2[4 * kk + 1], azB);
                    azC = ffma2(hp[4 * kk + 2], wz2[4 * kk + 2], azC);
                    azD = ffma2(hp[4 * kk + 3], wz2[4 * kk + 3], azD);
                }
                float2 nn = unpack2(fadd2(fadd2(anA, anB), fadd2(anC, anD)));
                float an = nn.x + nn.y + bn;
                float ng = tanha(fmaf(rg, an, xn0));

                float2 zz = unpack2(fadd2(fadd2(azA, azB), fadd2(azC, azD)));
                float zg = fsig(xz0 + zz.x + zz.y + bz);

                h = fmaf(zg, h - ng, ng);

                encb[t * GH_ + lane] = h;
                xr0 = xr1; xz0 = xz1; xn0 = xn1;
                xr1 = xr2; xz1 = xz2; xn1 = xn2;
            }
        }
        return;
    }

    // =========================== GEMM ===========================
    {
        int j   = bid - NGRUB_;
        int tg  = tid >> 4;
        int gg  = tid & 15;
        int tb  = tg * 8;
        int gbase = gg * 6;

        int s_tok0 = tid >> 2;
        int s_kq   = (tid & 3) * 4;

        float bias[6];
#pragma unroll
        for (int jj = 0; jj < 6; jj++) bias[jj] = __ldg(&b_ih[gbase + jj]);

        for (int ts = 0; ts < 2; ts++) {
            int t    = j + ts * NGEMB_;
            int base = t * TM_;

            ull acc[4][6];
#pragma unroll
            for (int p = 0; p < 4; p++)
#pragma unroll
                for (int jj = 0; jj < 6; jj++) acc[p][jj] = 0ull;

            float4 pa[2];
            float4 pw[6];

            {
#pragma unroll
                for (int q = 0; q < 2; q++)
                    pa[q] = *reinterpret_cast<const float4*>(
                        g_seq + (size_t)(base + s_tok0 + q * 32) * GIN_ + s_kq);
                const float4* wsrc = reinterpret_cast<const float4*>(g_wt);
#pragma unroll
                for (int q = 0; q < 6; q++)
                    pw[q] = wsrc[q * 128 + tid];
            }
            {
#pragma unroll
                for (int q = 0; q < 2; q++) {
                    int tok = s_tok0 + q * 32;
                    sa[0][s_kq + 0][tok] = pa[q].x;
                    sa[0][s_kq + 1][tok] = pa[q].y;
                    sa[0][s_kq + 2][tok] = pa[q].z;
                    sa[0][s_kq + 3][tok] = pa[q].w;
                }
#pragma unroll
                for (int q = 0; q < 6; q++) {
                    int i = q * 128 + tid;
                    int k = i / 48;
                    int c4 = i - k * 48;
                    *reinterpret_cast<float4*>(&sw[0][k][c4 * 4]) = pw[q];
                }
            }
            __syncthreads();

            for (int kt = 0; kt < NKT_; kt++) {
                int cur = kt & 1;
                if (kt + 1 < NKT_) {
                    int k0 = (kt + 1) * KT_;
#pragma unroll
                    for (int q = 0; q < 2; q++)
                        pa[q] = *reinterpret_cast<const float4*>(
                            g_seq + (size_t)(base + s_tok0 + q * 32) * GIN_ + k0 + s_kq);
                    const float4* wsrc = reinterpret_cast<const float4*>(g_wt + k0 * (2 * G3_));
#pragma unroll
                    for (int q = 0; q < 6; q++)
                        pw[q] = wsrc[q * 128 + tid];
                }

#pragma unroll
                for (int k = 0; k < KT_; k++) {
                    const ull* ap = reinterpret_cast<const ull*>(&sa[cur][k][tb]);
                    ull a0 = ap[0], a1 = ap[1], a2 = ap[2], a3 = ap[3];
                    const ull* wp = reinterpret_cast<const ull*>(&sw[cur][k][2 * gbase]);
                    ull w0 = wp[0], w1 = wp[1], w2 = wp[2], w3 = wp[3], w4 = wp[4], w5 = wp[5];
                    acc[0][0] = ffma2(a0, w0, acc[0][0]);
                    acc[1][0] = ffma2(a1, w0, acc[1][0]);
                    acc[2][0] = ffma2(a2, w0, acc[2][0]);
                    acc[3][0] = ffma2(a3, w0, acc[3][0]);
                    acc[0][1] = ffma2(a0, w1, acc[0][1]);
                    acc[1][1] = ffma2(a1, w1, acc[1][1]);
                    acc[2][1] = ffma2(a2, w1, acc[2][1]);
                    acc[3][1] = ffma2(a3, w1, acc[3][1]);
                    acc[0][2] = ffma2(a0, w2, acc[0][2]);
                    acc[1][2] = ffma2(a1, w2, acc[1][2]);
                    acc[2][2] = ffma2(a2, w2, acc[2][2]);
                    acc[3][2] = ffma2(a3, w2, acc[3][2]);
                    acc[0][3] = ffma2(a0, w3, acc[0][3]);
                    acc[1][3] = ffma2(a1, w3, acc[1][3]);
                    acc[2][3] = ffma2(a2, w3, acc[2][3]);
                    acc[3][3] = ffma2(a3, w3, acc[3][3]);
                    acc[0][4] = ffma2(a0, w4, acc[0][4]);
                    acc[1][4] = ffma2(a1, w4, acc[1][4]);
                    acc[2][4] = ffma2(a2, w4, acc[2][4]);
                    acc[3][4] = ffma2(a3, w4, acc[3][4]);
                    acc[0][5] = ffma2(a0, w5, acc[0][5]);
                    acc[1][5] = ffma2(a1, w5, acc[1][5]);
                    acc[2][5] = ffma2(a2, w5, acc[2][5]);
                    acc[3][5] = ffma2(a3, w5, acc[3][5]);
                }

                if (kt + 1 < NKT_) {
                    int nxt = cur ^ 1;
#pragma unroll
                    for (int q = 0; q < 2; q++) {
                        int tok = s_tok0 + q * 32;
                        sa[nxt][s_kq + 0][tok] = pa[q].x;
                        sa[nxt][s_kq + 1][tok] = pa[q].y;
                        sa[nxt][s_kq + 2][tok] = pa[q].z;
                        sa[nxt][s_kq + 3][tok] = pa[q].w;
                    }
#pragma unroll
                    for (int q = 0; q < 6; q++) {
                        int i = q * 128 + tid;
                        int k = i / 48;
                        int c4 = i - k * 48;
                        *reinterpret_cast<float4*>(&sw[nxt][k][c4 * 4]) = pw[q];
                    }
                }
                __syncthreads();
            }

#pragma unroll
            for (int p = 0; p < 4; p++) {
                int tok0 = base + tb + 2 * p;
                float lo[6], hi[6];
#pragma unroll
                for (int jj = 0; jj < 6; jj++) {
                    float2 v = unpack2(acc[p][jj]);
                    lo[jj] = v.x + bias[jj];
                    hi[jj] = v.y + bias[jj];
                }
                int b0 = tok0 & (B_ - 1), t0 = tok0 >> 6;
                int b1v = (tok0 + 1) & (B_ - 1), t1v = (tok0 + 1) >> 6;
                float2* o0 = reinterpret_cast<float2*>(g_xp + ((size_t)b0 * H_ + t0) * G3_ + gbase);
                float2* o1 = reinterpret_cast<float2*>(g_xp + ((size_t)b1v * H_ + t1v) * G3_ + gbase);
                o0[0] = make_float2(lo[0], lo[1]);
                o0[1] = make_float2(lo[2], lo[3]);
                o0[2] = make_float2(lo[4], lo[5]);
                o1[0] = make_float2(hi[0], hi[1]);
                o1[1] = make_float2(hi[2], hi[3]);
                o1[2] = make_float2(hi[4], hi[5]);
            }

            // publish this timestep
            __threadfence();
            __syncthreads();
            if (tid == 0)
                atomicAdd(&g_cnt[t / CH_], 1);
            __syncthreads();   // smem safe for next ts
        }
    }
}

// =====================================================================
// Kernel 3: attention scores (round-4 proven)
// =====================================================================
__global__ void __launch_bounds__(128) k_scores(
    const float* __restrict__ w1, const float* __restrict__ b1,
    const float* __restrict__ w2, const float* __restrict__ b2)
{
    __shared__ __align__(16) float sw1[GH_ * GH_];
    __shared__ __align__(16) float sw2[GH_ * GH_];
    __shared__ float sb1[GH_], sb2[GH_];

    int tid = threadIdx.x;
#pragma unroll
    for (int q = 0; q < 8; q++) {
        sw1[q * 128 + tid] = w1[q * 128 + tid];
        sw2[q * 128 + tid] = w2[q * 128 + tid];
    }
    if (tid < GH_) { sb1[tid] = b1[tid]; sb2[tid] = b2[tid]; }
    __syncthreads();

    int tok = blockIdx.x * 128 + tid;
    const float* erow = g_enc + (size_t)tok * GH_;

    ull e2[16];
#pragma unroll
    for (int i = 0; i < 8; i++) {
        ulonglong2 v = reinterpret_cast<const ulonglong2*>(erow)[i];
        e2[2 * i] = v.x; e2[2 * i + 1] = v.y;
    }

    ull h2[16];
#pragma unroll 4
    for (int j = 0; j < GH_; j += 2) {
        const ulonglong2* wA = reinterpret_cast<const ulonglong2*>(sw1 + j * GH_);
        const ulonglong2* wB = reinterpret_cast<const ulonglong2*>(sw1 + (j + 1) * GH_);
        ull a0 = 0ull, a1 = 0ull, c0 = 0ull, c1 = 0ull;
#pragma unroll
        for (int k = 0; k < 8; k++) {
            ulonglong2 wa = wA[k], wb = wB[k];
            a0 = ffma2(e2[2 * k],     wa.x, a0);
            a1 = ffma2(e2[2 * k + 1], wa.y, a1);
            c0 = ffma2(e2[2 * k],     wb.x, c0);
            c1 = ffma2(e2[2 * k + 1], wb.y, c1);
        }
        float2 fa = unpack2(fadd2(a0, a1));
        float2 fc = unpack2(fadd2(c0, c1));
        h2[j >> 1] = pack2(tanha(fa.x + fa.y + sb1[j]),
                           tanha(fc.x + fc.y + sb1[j + 1]));
    }

    float outv[GH_];
#pragma unroll 4
    for (int g = 0; g < GH_; g += 2) {
        const ulonglong2* wA = reinterpret_cast<const ulonglong2*>(sw2 + g * GH_);
        const ulonglong2* wB = reinterpret_cast<const ulonglong2*>(sw2 + (g + 1) * GH_);
        ull a0 = 0ull, a1 = 0ull, c0 = 0ull, c1 = 0ull;
#pragma unroll
        for (int k = 0; k < 8; k++) {
            ulonglong2 wa = wA[k], wb = wB[k];
            a0 = ffma2(h2[2 * k],     wa.x, a0);
            a1 = ffma2(h2[2 * k + 1], wa.y, a1);
            c0 = ffma2(h2[2 * k],     wb.x, c0);
            c1 = ffma2(h2[2 * k + 1], wb.y, c1);
        }
        float2 fa = unpack2(fadd2(a0, a1));
        float2 fc = unpack2(fadd2(c0, c1));
        outv[g]     = fa.x + fa.y + sb2[g];
        outv[g + 1] = fc.x + fc.y + sb2[g + 1];
    }

    float* arow = g_att + (size_t)tok * GH_;
#pragma unroll
    for (int i = 0; i < 8; i++)
        reinterpret_cast<float4*>(arow)[i] =
            make_float4(outv[4 * i], outv[4 * i + 1], outv[4 * i + 2], outv[4 * i + 3]);
}

// =====================================================================
// Kernel 4: softmax over t + pool + head. (proven)
// =====================================================================
__global__ void __launch_bounds__(512) k_pool(
    const float* __restrict__ w3, const float* __restrict__ b3,
    float* __restrict__ out)
{
    int b    = blockIdx.x;
    int tid  = threadIdx.x;
    int part = tid >> 3;
    int gq   = tid & 7;
    int wid  = tid >> 5;

    const float4* encb = reinterpret_cast<const float4*>(g_enc + (size_t)b * H_ * GH_);
    const float4* attb = reinterpret_cast<const float4*>(g_att + (size_t)b * H_ * GH_);

    __shared__ float4 red[16][8];
    __shared__ float4 redp[16][8];
    __shared__ float4 mg4s[8];
    __shared__ float pooled[GH_];

    float4 m = make_float4(-1e30f, -1e30f, -1e30f, -1e30f);
    for (int t = part; t < H_; t += 64)
        m = max4(m, attb[t * 8 + gq]);
#pragma unroll
    for (int s = 8; s <= 16; s <<= 1) {
        m.x = fmaxf(m.x, __shfl_xor_sync(0xffffffffu, m.x, s));
        m.y = fmaxf(m.y, __shfl_xor_sync(0xffffffffu, m.y, s));
        m.z = fmaxf(m.z, __shfl_xor_sync(0xffffffffu, m.z, s));
        m.w = fmaxf(m.w, __shfl_xor_sync(0xffffffffu, m.w, s));
    }
    if ((tid & 31) < 8) red[wid][gq] = m;
    __syncthreads();
    if (tid < 8) {
        float4 mm = red[0][tid];
#pragma unroll
        for (int p = 1; p < 16; p++) mm = max4(mm, red[p][tid]);
        mg4s[tid] = mm;
    }
    __syncthreads();
    float4 mg = mg4s[gq];

    float4 se = make_float4(0.f, 0.f, 0.f, 0.f);
    float4 pw = make_float4(0.f, 0.f, 0.f, 0.f);
    for (int t = part; t < H_; t += 64) {
        float4 a = attb[t * 8 + gq];
        float4 e = encb[t * 8 + gq];
        float ex0 = __expf(a.x - mg.x);
        float ex1 = __expf(a.y - mg.y);
        float ex2v = __expf(a.z - mg.z);
        float ex3 = __expf(a.w - mg.w);
        se.x += ex0; se.y += ex1; se.z += ex2v; se.w += ex3;
        pw.x = fmaf(ex0, e.x, pw.x);
        pw.y = fmaf(ex1, e.y, pw.y);
        pw.z = fmaf(ex2v, e.z, pw.z);
        pw.w = fmaf(ex3, e.w, pw.w);
    }
#pragma unroll
    for (int s = 8; s <= 16; s <<= 1) {
        se.x += __shfl_xor_sync(0xffffffffu, se.x, s);
        se.y += __shfl_xor_sync(0xffffffffu, se.y, s);
        se.z += __shfl_xor_sync(0xffffffffu, se.z, s);
        se.w += __shfl_xor_sync(0xffffffffu, se.w, s);
        pw.x += __shfl_xor_sync(0xffffffffu, pw.x, s);
        pw.y += __shfl_xor_sync(0xffffffffu, pw.y, s);
        pw.z += __shfl_xor_sync(0xffffffffu, pw.z, s);
        pw.w += __shfl_xor_sync(0xffffffffu, pw.w, s);
    }
    if ((tid & 31) < 8) { red[wid][gq] = se; redp[wid][gq] = pw; }
    __syncthreads();
    if (tid < 8) {
        float4 ts = red[0][tid];
        float4 tp = redp[0][tid];
#pragma unroll
        for (int p = 1; p < 16; p++) {
            float4 s1 = red[p][tid];
            float4 p1 = redp[p][tid];
            ts.x += s1.x; ts.y += s1.y; ts.z += s1.z; ts.w += s1.w;
            tp.x += p1.x; tp.y += p1.y; tp.z += p1.z; tp.w += p1.w;
        }
        pooled[tid * 4 + 0] = tp.x / ts.x;
        pooled[tid * 4 + 1] = tp.y / ts.y;
        pooled[tid * 4 + 2] = tp.z / ts.z;
        pooled[tid * 4 + 3] = tp.w / ts.w;
    }
    __syncthreads();

    if (tid < 64) {
        int o  = tid >> 5;
        int gg = tid & 31;
        float v = pooled[gg] * __ldg(&w3[o * GH_ + gg]);
#pragma unroll
        for (int s = 16; s > 0; s >>= 1)
            v += __shfl_xor_sync(0xffffffffu, v, s);
        if (gg == 0)
            out[b * 2 + o] = v + __ldg(&b3[o]);
    }
}

// =====================================================================
extern "C" void kernel_launch(void* const* d_in, const int* in_sizes, int n_in,
                              void* d_out, int out_size)
{
    const float* x     = (const float*)d_in[0];
    const float* p_w   = (const float*)d_in[1];
    const float* p_b   = (const float*)d_in[2];
    const float* dcn_w = (const float*)d_in[3];
    const float* dcn_b = (const float*)d_in[4];
    const float* w_ih  = (const float*)d_in[5];
    const float* w_hh  = (const float*)d_in[6];
    const float* b_ih  = (const float*)d_in[7];
    const float* b_hh  = (const float*)d_in[8];
    const float* w1    = (const float*)d_in[9];
    const float* b1    = (const float*)d_in[10];
    const float* w2    = (const float*)d_in[11];
    const float* b2    = (const float*)d_in[12];
    const float* w3    = (const float*)d_in[13];
    const float* b3    = (const float*)d_in[14];
    float* out = (float*)d_out;

    {
        int total   = B_ * H_ * WO_;
        int threads = 128;
        int blocks  = (total + threads - 1) / threads;
        k_deform<<<blocks, threads>>>(x, p_w, p_b, dcn_w, dcn_b, w_ih);
    }
    {
        k_mid<<<NBLK_, 128>>>(b_ih, w_hh, b_hh);    // 271 blocks: 16 gru + 255 gemm
    }
    {
        k_scores<<<NTOK_ / 128, 128>>>(w1, b1, w2, b2);  // 255 blocks
    }
    {
        k_pool<<<B_, 512>>>(w3, b3, out);
    }
}